// round 16
// baseline (speedup 1.0000x reference)
#include <cuda_runtime.h>
#include <cuda_bf16.h>
#include <math.h>
#include <stdint.h>

// ---------------- problem constants ----------------
#define Bc    2
#define Tc    1024
#define Ec    1024
#define Hc    16
#define Dc    64
#define NRELc 529
#define BHc   (Bc*Hc)
#define FFc   (4*Ec)
#define INV_SQRT_D 0.125f
#define INV_SQRT3  0.57735026918962576451f

// ---------------- scratch (device globals; allocation-free) ----------------
__device__ float g_q  [BHc*Tc*Dc];
__device__ float g_k  [BHc*Tc*Dc];
__device__ float g_v  [BHc*Tc*Dc];
__device__ float g_qrk[BHc*Tc*65];
__device__ float g_lr1[BHc*Tc*NRELc];
__device__ float g_lr2[BHc*NRELc*Tc];
__device__ float g_x2 [Bc*Tc*Ec];

__device__ __nv_bfloat16 g_actA_hi[Bc*Tc*Ec];
__device__ __nv_bfloat16 g_actA_lo[Bc*Tc*Ec];
__device__ __nv_bfloat16 g_actB_hi[Bc*Tc*FFc];
__device__ __nv_bfloat16 g_actB_lo[Bc*Tc*FFc];

// bf16 split copies of q,k (head-major) and LR tables
__device__ __nv_bfloat16 g_qh[BHc*Tc*Dc], g_ql[BHc*Tc*Dc];
__device__ __nv_bfloat16 g_kh[BHc*Tc*Dc], g_kl[BHc*Tc*Dc];
__device__ __nv_bfloat16 g_lrqh[Hc*NRELc*Dc], g_lrql[Hc*NRELc*Dc];
__device__ __nv_bfloat16 g_lrkh[Hc*NRELc*Dc], g_lrkl[Hc*NRELc*Dc];

#define WOFF_QKV 0
#define WOFF_PROJ (3072*1024)
#define WOFF_FC  (WOFF_PROJ + 1024*1024)
#define WOFF_FP  (WOFF_FC + 4096*1024)
#define WT_TOTAL (WOFF_FP + 1024*4096)
__device__ __nv_bfloat16 g_wt_hi[WT_TOTAL];
__device__ __nv_bfloat16 g_wt_lo[WT_TOTAL];

// ---------------- helpers ----------------
__device__ __forceinline__ float warp_sum(float v) {
    #pragma unroll
    for (int o = 16; o; o >>= 1) v += __shfl_xor_sync(0xffffffffu, v, o);
    return v;
}
__device__ __forceinline__ float gelu_f(float v) {
    const float c = 0.7978845608028654f;
    float t = tanhf(c * (v + 0.044715f * v * v * v));
    return 0.5f * v * (1.f + t);
}
__device__ __forceinline__ uint32_t smem_u32(const void* p) {
    uint32_t a;
    asm("{ .reg .u64 t; cvta.to.shared.u64 t, %1; cvt.u32.u64 %0, t; }" : "=r"(a) : "l"(p));
    return a;
}
__device__ __forceinline__ uint32_t pack_bf2(__nv_bfloat16 a, __nv_bfloat16 b) {
    __nv_bfloat162 t; t.x = a; t.y = b;
    return *(uint32_t*)&t;
}
__device__ __forceinline__ void ldsm4(uint32_t& r0, uint32_t& r1, uint32_t& r2, uint32_t& r3,
                                      uint32_t addr) {
    asm volatile("ldmatrix.sync.aligned.m8n8.x4.shared.b16 {%0,%1,%2,%3}, [%4];"
                 : "=r"(r0), "=r"(r1), "=r"(r2), "=r"(r3) : "r"(addr));
}
__device__ __forceinline__ void mma16816(float* d, uint32_t a0, uint32_t a1, uint32_t a2,
                                         uint32_t a3, uint32_t b0, uint32_t b1) {
    asm volatile(
        "mma.sync.aligned.m16n8k16.row.col.f32.bf16.bf16.f32 "
        "{%0,%1,%2,%3}, {%4,%5,%6,%7}, {%8,%9}, {%0,%1,%2,%3};"
        : "+f"(d[0]), "+f"(d[1]), "+f"(d[2]), "+f"(d[3])
        : "r"(a0), "r"(a1), "r"(a2), "r"(a3), "r"(b0), "r"(b1));
}
__device__ __forceinline__ void cpa16(uint32_t s, const void* g) {
    asm volatile("cp.async.ca.shared.global [%0], [%1], 16;" :: "r"(s), "l"(g));
}

// ---------------- LayerNorm -> split-bf16 ----------------
__global__ __launch_bounds__(256) void ln_bf16_kernel(
    const float* __restrict__ x, const float* __restrict__ gw,
    const float* __restrict__ gb,
    __nv_bfloat16* __restrict__ ohi, __nv_bfloat16* __restrict__ olo)
{
    int row = blockIdx.x;
    const float4* xr = (const float4*)(x + (size_t)row * Ec);
    float4 v = xr[threadIdx.x];
    __shared__ float red[8];
    __shared__ float bval[2];
    int wid = threadIdx.x >> 5, lane = threadIdx.x & 31;

    float s = warp_sum(v.x + v.y + v.z + v.w);
    if (lane == 0) red[wid] = s;
    __syncthreads();
    if (threadIdx.x == 0) {
        float t = 0.f;
        #pragma unroll
        for (int i = 0; i < 8; i++) t += red[i];
        bval[0] = t * (1.f / Ec);
    }
    __syncthreads();
    float mean = bval[0];
    float d0 = v.x - mean, d1 = v.y - mean, d2 = v.z - mean, d3 = v.w - mean;
    float q = warp_sum(d0*d0 + d1*d1 + d2*d2 + d3*d3);
    if (lane == 0) red[wid] = q;
    __syncthreads();
    if (threadIdx.x == 0) {
        float t = 0.f;
        #pragma unroll
        for (int i = 0; i < 8; i++) t += red[i];
        bval[1] = 1.f / (sqrtf(t / (float)(Ec - 1)) + 1e-6f);
    }
    __syncthreads();
    float inv = bval[1];
    float4 ww = ((const float4*)gw)[threadIdx.x];
    float4 bb = ((const float4*)gb)[threadIdx.x];
    float o0 = ww.x * d0 * inv + bb.x;
    float o1 = ww.y * d1 * inv + bb.y;
    float o2 = ww.z * d2 * inv + bb.z;
    float o3 = ww.w * d3 * inv + bb.w;

    __nv_bfloat16 h0 = __float2bfloat16(o0), h1 = __float2bfloat16(o1),
                  h2 = __float2bfloat16(o2), h3 = __float2bfloat16(o3);
    __nv_bfloat16 l0 = __float2bfloat16(o0 - __bfloat162float(h0));
    __nv_bfloat16 l1 = __float2bfloat16(o1 - __bfloat162float(h1));
    __nv_bfloat16 l2 = __float2bfloat16(o2 - __bfloat162float(h2));
    __nv_bfloat16 l3 = __float2bfloat16(o3 - __bfloat162float(h3));
    size_t base = (size_t)row * Ec + threadIdx.x * 4;
    *(uint2*)(ohi + base) = make_uint2(pack_bf2(h0,h1), pack_bf2(h2,h3));
    *(uint2*)(olo + base) = make_uint2(pack_bf2(l0,l1), pack_bf2(l2,l3));
}

// ---------------- weight transpose + split-bf16:  W[K,N] -> [N,K] hi/lo ----------------
__global__ __launch_bounds__(256) void transpose_conv_kernel(
    const float* __restrict__ W,
    __nv_bfloat16* __restrict__ Ohi, __nv_bfloat16* __restrict__ Olo,
    int K, int N)
{
    __shared__ float t[32][33];
    int n0 = blockIdx.x * 32, k0 = blockIdx.y * 32;
    int tx = threadIdx.x & 31, ty = threadIdx.x >> 5;
    #pragma unroll
    for (int i = ty; i < 32; i += 8)
        t[i][tx] = W[(size_t)(k0 + i) * N + n0 + tx];
    __syncthreads();
    #pragma unroll
    for (int i = ty; i < 32; i += 8) {
        float v = t[tx][i];
        __nv_bfloat16 h = __float2bfloat16(v);
        float lo = v - __bfloat162float(h);
        size_t o = (size_t)(n0 + i) * K + k0 + tx;
        Ohi[o] = h;
        Olo[o] = __float2bfloat16(lo);
    }
}

// ---------------- flat fp32 -> split-bf16 convert (LR tables) ----------------
__global__ __launch_bounds__(256) void conv_lr_kernel(
    const float* __restrict__ s, __nv_bfloat16* __restrict__ h, __nv_bfloat16* __restrict__ l)
{
    int i = blockIdx.x * 256 + threadIdx.x;
    float v = s[i];
    __nv_bfloat16 hh = __float2bfloat16(v);
    h[i] = hh;
    l[i] = __float2bfloat16(v - __bfloat162float(hh));
}

// ---------------- HMMA split-bf16 GEMM, cp.async 2-stage pipeline ----------------
// TERMS=3: Ah*Bh + Ah*Bl + Al*Bh.  TERMS=2: Ah*Bh + Ah*Bl (A quantized).
// MODE 2: bias+resid -> fp32 C | MODE 3: bias+gelu -> bf16 hi/lo
// MODE 4: QKV epilogue — bias, then scatter to head-major g_q/g_k/g_v (+ q,k bf16 hi/lo)
#define LDA 40
#define CHUNK_BYTES (128*LDA*2)
#define STAGE_BYTES (4*CHUNK_BYTES)
#define GEMM_SMEM   (2*STAGE_BYTES)
template<int MODE, int TERMS>
__global__ __launch_bounds__(256, 2) void mma_gemm(
    const __nv_bfloat16* __restrict__ Ahi, const __nv_bfloat16* __restrict__ Alo,
    const __nv_bfloat16* __restrict__ Bhi, const __nv_bfloat16* __restrict__ Blo,
    const float* __restrict__ bias, const float* __restrict__ resid,
    float* __restrict__ C,
    __nv_bfloat16* __restrict__ Ohi, __nv_bfloat16* __restrict__ Olo,
    int M, int N, int K)
{
    extern __shared__ __align__(16) __nv_bfloat16 dsm[];
    int tid = threadIdx.x, lane = tid & 31, wid = tid >> 5;
    int m0 = blockIdx.y * 128, n0 = blockIdx.x * 128;
    int wm = (wid & 1) * 64, wn = (wid >> 1) * 32;

    const __nv_bfloat16* gp0 = Ahi + (size_t)m0 * K;
    const __nv_bfloat16* gp1 = Alo + (size_t)m0 * K;
    const __nv_bfloat16* gp2 = Bhi + (size_t)n0 * K;
    const __nv_bfloat16* gp3 = Blo + (size_t)n0 * K;

    int lr = tid >> 2, lc = tid & 3;
    size_t go0 = (size_t)lr * K + lc * 8;
    size_t go1 = (size_t)(lr + 64) * K + lc * 8;
    uint32_t sb = smem_u32(dsm);
    uint32_t so0 = (uint32_t)(lr * LDA + lc * 8) * 2;
    uint32_t so1 = (uint32_t)((lr + 64) * LDA + lc * 8) * 2;

    float acc[4][4][4] = {};

    uint32_t a_off = (uint32_t)(((wm + (lane & 15)) * LDA + ((lane >> 4) << 3)) * 2);
    uint32_t b_off = (uint32_t)(((wn + ((lane >> 4) << 3) + (lane & 7)) * LDA +
                                 (((lane >> 3) & 1) << 3)) * 2);

    const int nch = K >> 5;
    {
        cpa16(sb + 0*CHUNK_BYTES + so0, gp0 + go0); cpa16(sb + 0*CHUNK_BYTES + so1, gp0 + go1);
        if (TERMS == 3) {
            cpa16(sb + 1*CHUNK_BYTES + so0, gp1 + go0); cpa16(sb + 1*CHUNK_BYTES + so1, gp1 + go1);
        }
        cpa16(sb + 2*CHUNK_BYTES + so0, gp2 + go0); cpa16(sb + 2*CHUNK_BYTES + so1, gp2 + go1);
        cpa16(sb + 3*CHUNK_BYTES + so0, gp3 + go0); cpa16(sb + 3*CHUNK_BYTES + so1, gp3 + go1);
        asm volatile("cp.async.commit_group;");
    }
    for (int ch = 0; ch < nch; ch++) {
        uint32_t cb = sb + (uint32_t)((ch & 1) ? STAGE_BYTES : 0);
        if (ch + 1 < nch) {
            uint32_t nb = sb + (uint32_t)(((ch + 1) & 1) ? STAGE_BYTES : 0);
            int kc = (ch + 1) << 5;
            cpa16(nb + 0*CHUNK_BYTES + so0, gp0 + go0 + kc); cpa16(nb + 0*CHUNK_BYTES + so1, gp0 + go1 + kc);
            if (TERMS == 3) {
                cpa16(nb + 1*CHUNK_BYTES + so0, gp1 + go0 + kc); cpa16(nb + 1*CHUNK_BYTES + so1, gp1 + go1 + kc);
            }
            cpa16(nb + 2*CHUNK_BYTES + so0, gp2 + go0 + kc); cpa16(nb + 2*CHUNK_BYTES + so1, gp2 + go1 + kc);
            cpa16(nb + 3*CHUNK_BYTES + so0, gp3 + go0 + kc); cpa16(nb + 3*CHUNK_BYTES + so1, gp3 + go1 + kc);
            asm volatile("cp.async.commit_group;");
            asm volatile("cp.async.wait_group 1;");
        } else {
            asm volatile("cp.async.wait_group 0;");
        }
        __syncthreads();

        uint32_t sA = cb, sAl = cb + CHUNK_BYTES, sB = cb + 2*CHUNK_BYTES, sBl = cb + 3*CHUNK_BYTES;
        #pragma unroll
        for (int ks = 0; ks < 2; ks++) {
            uint32_t kb = (uint32_t)(ks * 16 * 2);
            uint32_t ah[4][4], al[4][4];
            #pragma unroll
            for (int mt = 0; mt < 4; mt++) {
                uint32_t o = a_off + kb + (uint32_t)(mt * 16 * LDA * 2);
                ldsm4(ah[mt][0], ah[mt][1], ah[mt][2], ah[mt][3], sA + o);
                if (TERMS == 3)
                    ldsm4(al[mt][0], al[mt][1], al[mt][2], al[mt][3], sAl + o);
            }
            #pragma unroll
            for (int ntp = 0; ntp < 2; ntp++) {
                uint32_t o = b_off + kb + (uint32_t)(ntp * 16 * LDA * 2);
                uint32_t bh00, bh01, bh10, bh11, bl00, bl01, bl10, bl11;
                ldsm4(bh00, bh01, bh10, bh11, sB + o);
                ldsm4(bl00, bl01, bl10, bl11, sBl + o);
                #pragma unroll
                for (int mt = 0; mt < 4; mt++) {
                    mma16816(acc[mt][2*ntp+0], ah[mt][0], ah[mt][1], ah[mt][2], ah[mt][3], bh00, bh01);
                    mma16816(acc[mt][2*ntp+0], ah[mt][0], ah[mt][1], ah[mt][2], ah[mt][3], bl00, bl01);
                    if (TERMS == 3)
                        mma16816(acc[mt][2*ntp+0], al[mt][0], al[mt][1], al[mt][2], al[mt][3], bh00, bh01);
                    mma16816(acc[mt][2*ntp+1], ah[mt][0], ah[mt][1], ah[mt][2], ah[mt][3], bh10, bh11);
                    mma16816(acc[mt][2*ntp+1], ah[mt][0], ah[mt][1], ah[mt][2], ah[mt][3], bl10, bl11);
                    if (TERMS == 3)
                        mma16816(acc[mt][2*ntp+1], al[mt][0], al[mt][1], al[mt][2], al[mt][3], bh10, bh11);
                }
            }
        }
        __syncthreads();
    }

    int er = lane >> 2, ec = (lane & 3) * 2;
    #pragma unroll
    for (int mt = 0; mt < 4; mt++) {
        #pragma unroll
        for (int nt = 0; nt < 4; nt++) {
            int m = m0 + wm + mt * 16 + er;
            int n = n0 + wn + nt * 8 + ec;
            float bv0 = bias[n], bv1 = bias[n + 1];
            float v00 = acc[mt][nt][0] + bv0, v01 = acc[mt][nt][1] + bv1;
            float v10 = acc[mt][nt][2] + bv0, v11 = acc[mt][nt][3] + bv1;
            if (MODE == 4) {
                int which = n >> 10;
                int e = n & (Ec - 1);
                int h = e >> 6, d = e & 63;
                #pragma unroll
                for (int half = 0; half < 2; half++) {
                    int mm = m + half * 8;
                    float va = half ? v10 : v00;
                    float vb = half ? v11 : v01;
                    int b = mm >> 10, t = mm & (Tc - 1);
                    size_t o = (((size_t)(b * Hc + h)) * Tc + t) * Dc + d;
                    if (which == 2) {
                        *(float2*)(g_v + o) = make_float2(va, vb);
                    } else {
                        __nv_bfloat16 ha = __float2bfloat16(va), hb = __float2bfloat16(vb);
                        uint32_t hi = pack_bf2(ha, hb);
                        uint32_t lo = pack_bf2(__float2bfloat16(va - __bfloat162float(ha)),
                                               __float2bfloat16(vb - __bfloat162float(hb)));
                        if (which == 0) {
                            *(float2*)(g_q + o) = make_float2(va, vb);
                            *(uint32_t*)(g_qh + o) = hi;
                            *(uint32_t*)(g_ql + o) = lo;
                        } else {
                            *(float2*)(g_k + o) = make_float2(va, vb);
                            *(uint32_t*)(g_kh + o) = hi;
                            *(uint32_t*)(g_kl + o) = lo;
                        }
                    }
                }
                continue;
            }
            size_t g0 = (size_t)m * N + n;
            size_t g1 = (size_t)(m + 8) * N + n;
            if (MODE == 3) {
                v00 = gelu_f(v00); v01 = gelu_f(v01);
                v10 = gelu_f(v10); v11 = gelu_f(v11);
                __nv_bfloat16 h00 = __float2bfloat16(v00), h01 = __float2bfloat16(v01);
                __nv_bfloat16 h10 = __float2bfloat16(v10), h11 = __float2bfloat16(v11);
                *(uint32_t*)(Ohi + g0) = pack_bf2(h00, h01);
                *(uint32_t*)(Ohi + g1) = pack_bf2(h10, h11);
                *(uint32_t*)(Olo + g0) = pack_bf2(
                    __float2bfloat16(v00 - __bfloat162float(h00)),
                    __float2bfloat16(v01 - __bfloat162float(h01)));
                *(uint32_t*)(Olo + g1) = pack_bf2(
                    __float2bfloat16(v10 - __bfloat162float(h10)),
                    __float2bfloat16(v11 - __bfloat162float(h11)));
            } else {
                if (MODE == 2) {
                    v00 += resid[g0]; v01 += resid[g0 + 1];
                    v10 += resid[g1]; v11 += resid[g1 + 1];
                }
                *(float2*)(C + g0) = make_float2(v00, v01);
                *(float2*)(C + g1) = make_float2(v10, v11);
            }
        }
    }
}

// ---------------- batched HMMA NT GEMM (lr1 / lr2): C[bh] = scale * A @ B^T ----------------
__global__ __launch_bounds__(256, 2) void mma_gemm_bat(
    const __nv_bfloat16* __restrict__ Ahi, const __nv_bfloat16* __restrict__ Alo,
    int aStride, int aPerH,
    const __nv_bfloat16* __restrict__ Bhi, const __nv_bfloat16* __restrict__ Blo,
    int bStride, int bPerH,
    float* __restrict__ C, size_t cStride, int M, int N, int K, float scale)
{
    extern __shared__ __align__(16) __nv_bfloat16 dsm[];
    int tid = threadIdx.x, lane = tid & 31, wid = tid >> 5;
    int bh = blockIdx.z;
    int m0 = blockIdx.y * 128, n0 = blockIdx.x * 128;
    int wm = (wid & 1) * 64, wn = (wid >> 1) * 32;

    const __nv_bfloat16* pAh = Ahi + (size_t)(aPerH ? (bh & 15) : bh) * aStride;
    const __nv_bfloat16* pAl = Alo + (size_t)(aPerH ? (bh & 15) : bh) * aStride;
    const __nv_bfloat16* pBh = Bhi + (size_t)(bPerH ? (bh & 15) : bh) * bStride;
    const __nv_bfloat16* pBl = Blo + (size_t)(bPerH ? (bh & 15) : bh) * bStride;

    int lr = tid >> 2, lc = tid & 3;
    int ra0 = m0 + lr;      if (ra0 > M - 1) ra0 = M - 1;
    int ra1 = m0 + lr + 64; if (ra1 > M - 1) ra1 = M - 1;
    int rb0 = n0 + lr;      if (rb0 > N - 1) rb0 = N - 1;
    int rb1 = n0 + lr + 64; if (rb1 > N - 1) rb1 = N - 1;
    size_t gA0 = (size_t)ra0 * K + lc * 8, gA1 = (size_t)ra1 * K + lc * 8;
    size_t gB0 = (size_t)rb0 * K + lc * 8, gB1 = (size_t)rb1 * K + lc * 8;
    uint32_t sb = smem_u32(dsm);
    uint32_t so0 = (uint32_t)(lr * LDA + lc * 8) * 2;
    uint32_t so1 = (uint32_t)((lr + 64) * LDA + lc * 8) * 2;

    float acc[4][4][4] = {};

    uint32_t a_off = (uint32_t)(((wm + (lane & 15)) * LDA + ((lane >> 4) << 3)) * 2);
    uint32_t b_off = (uint32_t)(((wn + ((lane >> 4) << 3) + (lane & 7)) * LDA +
                                 (((lane >> 3) & 1) << 3)) * 2);

    const int nch = K >> 5;
    {
        cpa16(sb + 0*CHUNK_BYTES + so0, pAh + gA0); cpa16(sb + 0*CHUNK_BYTES + so1, pAh + gA1);
        cpa16(sb + 1*CHUNK_BYTES + so0, pAl + gA0); cpa16(sb + 1*CHUNK_BYTES + so1, pAl + gA1);
        cpa16(sb + 2*CHUNK_BYTES + so0, pBh + gB0); cpa16(sb + 2*CHUNK_BYTES + so1, pBh + gB1);
        cpa16(sb + 3*CHUNK_BYTES + so0, pBl + gB0); cpa16(sb + 3*CHUNK_BYTES + so1, pBl + gB1);
        asm volatile("cp.async.commit_group;");
    }
    for (int ch = 0; ch < nch; ch++) {
        uint32_t cb = sb + (uint32_t)((ch & 1) ? STAGE_BYTES : 0);
        if (ch + 1 < nch) {
            uint32_t nb = sb + (uint32_t)(((ch + 1) & 1) ? STAGE_BYTES : 0);
            int kc = (ch + 1) << 5;
            cpa16(nb + 0*CHUNK_BYTES + so0, pAh + gA0 + kc); cpa16(nb + 0*CHUNK_BYTES + so1, pAh + gA1 + kc);
            cpa16(nb + 1*CHUNK_BYTES + so0, pAl + gA0 + kc); cpa16(nb + 1*CHUNK_BYTES + so1, pAl + gA1 + kc);
            cpa16(nb + 2*CHUNK_BYTES + so0, pBh + gB0 + kc); cpa16(nb + 2*CHUNK_BYTES + so1, pBh + gB1 + kc);
            cpa16(nb + 3*CHUNK_BYTES + so0, pBl + gB0 + kc); cpa16(nb + 3*CHUNK_BYTES + so1, pBl + gB1 + kc);
            asm volatile("cp.async.commit_group;");
            asm volatile("cp.async.wait_group 1;");
        } else {
            asm volatile("cp.async.wait_group 0;");
        }
        __syncthreads();

        uint32_t sA = cb, sAl = cb + CHUNK_BYTES, sB = cb + 2*CHUNK_BYTES, sBl = cb + 3*CHUNK_BYTES;
        #pragma unroll
        for (int ks = 0; ks < 2; ks++) {
            uint32_t kb = (uint32_t)(ks * 16 * 2);
            uint32_t ah[4][4], al[4][4];
            #pragma unroll
            for (int mt = 0; mt < 4; mt++) {
                uint32_t o = a_off + kb + (uint32_t)(mt * 16 * LDA * 2);
                ldsm4(ah[mt][0], ah[mt][1], ah[mt][2], ah[mt][3], sA + o);
                ldsm4(al[mt][0], al[mt][1], al[mt][2], al[mt][3], sAl + o);
            }
            #pragma unroll
            for (int ntp = 0; ntp < 2; ntp++) {
                uint32_t o = b_off + kb + (uint32_t)(ntp * 16 * LDA * 2);
                uint32_t bh00, bh01, bh10, bh11, bl00, bl01, bl10, bl11;
                ldsm4(bh00, bh01, bh10, bh11, sB + o);
                ldsm4(bl00, bl01, bl10, bl11, sBl + o);
                #pragma unroll
                for (int mt = 0; mt < 4; mt++) {
                    mma16816(acc[mt][2*ntp+0], ah[mt][0], ah[mt][1], ah[mt][2], ah[mt][3], bh00, bh01);
                    mma16816(acc[mt][2*ntp+0], ah[mt][0], ah[mt][1], ah[mt][2], ah[mt][3], bl00, bl01);
                    mma16816(acc[mt][2*ntp+0], al[mt][0], al[mt][1], al[mt][2], al[mt][3], bh00, bh01);
                    mma16816(acc[mt][2*ntp+1], ah[mt][0], ah[mt][1], ah[mt][2], ah[mt][3], bh10, bh11);
                    mma16816(acc[mt][2*ntp+1], ah[mt][0], ah[mt][1], ah[mt][2], ah[mt][3], bl10, bl11);
                    mma16816(acc[mt][2*ntp+1], al[mt][0], al[mt][1], al[mt][2], al[mt][3], bh10, bh11);
                }
            }
        }
        __syncthreads();
    }

    int er = lane >> 2, ec = (lane & 3) * 2;
    float* Cb = C + (size_t)bh * cStride;
    #pragma unroll
    for (int mt = 0; mt < 4; mt++) {
        #pragma unroll
        for (int nt = 0; nt < 4; nt++) {
            int m = m0 + wm + mt * 16 + er;
            int n = n0 + wn + nt * 8 + ec;
            if (m < M) {
                if (n     < N) Cb[(size_t)m * N + n]     = acc[mt][nt][0] * scale;
                if (n + 1 < N) Cb[(size_t)m * N + n + 1] = acc[mt][nt][1] * scale;
            }
            if (m + 8 < M) {
                if (n     < N) Cb[(size_t)(m + 8) * N + n]     = acc[mt][nt][2] * scale;
                if (n + 1 < N) Cb[(size_t)(m + 8) * N + n + 1] = acc[mt][nt][3] * scale;
            }
        }
    }
}

// ---------------- batched NT GEMM (qrk only) ----------------
__global__ __launch_bounds__(256) void ntgemm_kernel(
    const float* __restrict__ A, int strideA, int aModH,
    const float* __restrict__ Bm, int strideB, int bModH,
    float* __restrict__ C, size_t strideC, int M, int N, float scale)
{
    int bh = blockIdx.z;
    const float* Ab = A  + (size_t)(aModH ? (bh % Hc) : bh) * strideA;
    const float* Bb = Bm + (size_t)(bModH ? (bh % Hc) : bh) * strideB;
    float* Cb = C + (size_t)bh * strideC;
    int m0 = blockIdx.y * 64, n0 = blockIdx.x * 64;
    __shared__ float As[64][68];
    __shared__ float Bs[64][68];
    int tid = threadIdx.x;
    int tr = tid >> 4, tc4 = (tid & 15) * 4;
    #pragma unroll
    for (int p = 0; p < 4; p++) {
        int r = p * 16 + tr;
        float4 a = make_float4(0.f, 0.f, 0.f, 0.f);
        if (m0 + r < M) a = *(const float4*)(Ab + (size_t)(m0 + r) * Dc + tc4);
        As[tc4+0][r] = a.x; As[tc4+1][r] = a.y; As[tc4+2][r] = a.z; As[tc4+3][r] = a.w;
        float4 b4 = make_float4(0.f, 0.f, 0.f, 0.f);
        if (n0 + r < N) b4 = *(const float4*)(Bb + (size_t)(n0 + r) * Dc + tc4);
        Bs[tc4+0][r] = b4.x; Bs[tc4+1][r] = b4.y; Bs[tc4+2][r] = b4.z; Bs[tc4+3][r] = b4.w;
    }
    __syncthreads();
    int ty = tid >> 4, tx = tid & 15;
    float acc[4][4] = {};
    #pragma unroll
    for (int k = 0; k < 64; k++) {
        float af[4], bf[4];
        *(float4*)af = *(const float4*)&As[k][ty*4];
        *(float4*)bf = *(const float4*)&Bs[k][tx*4];
        #pragma unroll
        for (int i = 0; i < 4; i++)
            #pragma unroll
            for (int j = 0; j < 4; j++)
                acc[i][j] = fmaf(af[i], bf[j], acc[i][j]);
    }
    #pragma unroll
    for (int i = 0; i < 4; i++) {
        int m = m0 + ty*4 + i;
        if (m >= M) continue;
        #pragma unroll
        for (int j = 0; j < 4; j++) {
            int n = n0 + tx*4 + j;
            if (n < N) Cb[(size_t)m * N + n] = acc[i][j] * scale;
        }
    }
}

// ---------------- fused attention ----------------
#define FAS_Q 0
#define FAS_K (64*68)
#define FAS_V (2*64*68)
#define FAS_P (3*64*68)
#define FAS_W (3*64*68 + 64*65)
#define FAS_M (FAS_W + 2*64*68)
#define FAS_S (FAS_M + 64)
#define FAS_RW (FAS_S + 64)
#define FAS_TOT (FAS_RW + 64)
#define FA_BYTES (FAS_TOT * 4)

__global__ __launch_bounds__(256, 2) void fused_attn_kernel(
    const float* __restrict__ tds, const int* __restrict__ rel,
    const int* __restrict__ lrmap, const float* __restrict__ relw,
    const float* __restrict__ rv)
{
    extern __shared__ float fs[];
    int it = (Tc/64 - 1) - blockIdx.x;
    int bh = blockIdx.y;
    int b = bh >> 4, h = bh & 15;
    int i0 = it * 64;
    int tid = threadIdx.x;
    int tr = tid >> 4, tc4 = (tid & 15) * 4;
    int ty = tid >> 4, tx = tid & 15;

    const float* Qg = g_q + (size_t)bh * Tc * Dc;
    const float* Kg = g_k + (size_t)bh * Tc * Dc;
    const float* Vg = g_v + (size_t)bh * Tc * Dc;

    #pragma unroll
    for (int p = 0; p < 4; p++) {
        int r = p * 16 + tr;
        float4 a = *(const float4*)(Qg + (size_t)(i0 + r) * Dc + tc4);
        fs[FAS_Q + (tc4+0)*68 + r] = a.x; fs[FAS_Q + (tc4+1)*68 + r] = a.y;
        fs[FAS_Q + (tc4+2)*68 + r] = a.z; fs[FAS_Q + (tc4+3)*68 + r] = a.w;
    }
    if (tid < 64) fs[FAS_RW + tid] = relw[tid * Hc + h];

    float rm[4] = {-1e30f, -1e30f, -1e30f, -1e30f};
    float rs[4] = {0.f, 0.f, 0.f, 0.f};
    float av[4][4] = {};

    for (int jt = 0; jt <= it; jt++) {
        int j0 = jt * 64;
        #pragma unroll
        for (int p = 0; p < 4; p++) {
            int r = p * 16 + tr;
            float4 kq = *(const float4*)(Kg + (size_t)(j0 + r) * Dc + tc4);
            fs[FAS_K + (tc4+0)*68 + r] = kq.x; fs[FAS_K + (tc4+1)*68 + r] = kq.y;
            fs[FAS_K + (tc4+2)*68 + r] = kq.z; fs[FAS_K + (tc4+3)*68 + r] = kq.w;
            float4 vv = *(const float4*)(Vg + (size_t)(j0 + r) * Dc + tc4);
            *(float4*)&fs[FAS_V + r*68 + tc4] = vv;
        }
        __syncthreads();

        float aw[4][4] = {};
        #pragma unroll
        for (int k = 0; k < 64; k++) {
            float af[4], bf[4];
            *(float4*)af = *(const float4*)&fs[FAS_Q + k*68 + ty*4];
            *(float4*)bf = *(const float4*)&fs[FAS_K + k*68 + tx*4];
            #pragma unroll
            for (int i = 0; i < 4; i++)
                #pragma unroll
                for (int j = 0; j < 4; j++)
                    aw[i][j] = fmaf(af[i], bf[j], aw[i][j]);
        }

        bool diag = (jt == it);
        bool far = (jt < it - 1);
        #pragma unroll
        for (int ii = 0; ii < 4; ii++) {
            int i = i0 + ty*4 + ii;
            const float* qrk_row = g_qrk + ((size_t)bh * Tc + i) * 65;
            const float* lr1_row = g_lr1 + ((size_t)bh * Tc + i) * NRELc;
            float qrk0 = qrk_row[0];
            size_t base_b  = ((size_t)b  * Tc + i) * Tc;
            size_t base_bh = ((size_t)bh * Tc + i) * Tc;
            float4 td4 = *(const float4*)(tds + base_bh + j0 + tx*4);
            int4  re4  = *(const int4*)(rel + base_b + j0 + tx*4);
            int4  lm4  = *(const int4*)(lrmap + base_b + j0 + tx*4);
            float tdv[4] = {td4.x, td4.y, td4.z, td4.w};
            int   rev[4] = {re4.x, re4.y, re4.z, re4.w};
            int   lmv[4] = {lm4.x, lm4.y, lm4.z, lm4.w};
            #pragma unroll
            for (int jj = 0; jj < 4; jj++) {
                int j = j0 + tx*4 + jj;
                float wv;
                if (diag && j > i) {
                    wv = -1e30f;
                } else {
                    float qv = qrk0;
                    if (!far) {
                        int rid = j - i + 32; if (rid < 0) rid = 0;
                        qv = qrk_row[rid];
                    }
                    wv = (aw[ii][jj] + qv) * INV_SQRT_D;
                    wv *= fs[FAS_RW + rev[jj]];
                    wv += tdv[jj];
                    int lm = lmv[jj];
                    wv = (wv + lr1_row[lm] + g_lr2[((size_t)bh * NRELc + lm) * Tc + j]) * INV_SQRT3;
                }
                aw[ii][jj] = wv;
            }
            if (jt >= it - 1)
                *(float4*)&fs[FAS_W + (jt&1)*64*68 + (ty*4+ii)*68 + tx*4] =
                    make_float4(aw[ii][0], aw[ii][1], aw[ii][2], aw[ii][3]);
        }

        float tm[4], alpha[4], rsum[4];
        #pragma unroll
        for (int ii = 0; ii < 4; ii++) {
            tm[ii] = fmaxf(fmaxf(aw[ii][0], aw[ii][1]), fmaxf(aw[ii][2], aw[ii][3]));
            #pragma unroll
            for (int o = 1; o < 16; o <<= 1)
                tm[ii] = fmaxf(tm[ii], __shfl_xor_sync(0xffffffffu, tm[ii], o));
            float mn = fmaxf(rm[ii], tm[ii]);
            alpha[ii] = __expf(rm[ii] - mn);
            rm[ii] = mn;
            float e0 = __expf(aw[ii][0] - mn), e1 = __expf(aw[ii][1] - mn);
            float e2 = __expf(aw[ii][2] - mn), e3 = __expf(aw[ii][3] - mn);
            aw[ii][0] = e0; aw[ii][1] = e1; aw[ii][2] = e2; aw[ii][3] = e3;
            rsum[ii] = e0 + e1 + e2 + e3;
            #pragma unroll
            for (int o = 1; o < 16; o <<= 1)
                rsum[ii] += __shfl_xor_sync(0xffffffffu, rsum[ii], o);
            rs[ii] = rs[ii] * alpha[ii] + rsum[ii];
        }

        #pragma unroll
        for (int ii = 0; ii < 4; ii++)
            #pragma unroll
            for (int jj = 0; jj < 4; jj++)
                fs[FAS_P + (tx*4+jj)*65 + ty*4+ii] = aw[ii][jj];
        __syncthreads();

        #pragma unroll
        for (int ii = 0; ii < 4; ii++)
            #pragma unroll
            for (int jj = 0; jj < 4; jj++)
                av[ii][jj] *= alpha[ii];
        #pragma unroll
        for (int k = 0; k < 64; k++) {
            float pf[4], vf[4];
            pf[0] = fs[FAS_P + k*65 + ty*4+0];
            pf[1] = fs[FAS_P + k*65 + ty*4+1];
            pf[2] = fs[FAS_P + k*65 + ty*4+2];
            pf[3] = fs[FAS_P + k*65 + ty*4+3];
            *(float4*)vf = *(const float4*)&fs[FAS_V + k*68 + tx*4];
            #pragma unroll
            for (int i = 0; i < 4; i++)
                #pragma unroll
                for (int j = 0; j < 4; j++)
                    av[i][j] = fmaf(pf[i], vf[j], av[i][j]);
        }
        __syncthreads();
    }

    if (tx == 0) {
        #pragma unroll
        for (int ii = 0; ii < 4; ii++) {
            fs[FAS_M + ty*4+ii] = rm[ii];
            fs[FAS_S + ty*4+ii] = 1.f / rs[ii];
        }
    }
    __syncthreads();

    for (int idx = tid; idx < 65*64; idx += 256)
        fs[FAS_V + idx] = rv[idx];
    #pragma unroll
    for (int q = 0; q < 8; q++) {
        int idx = tid * 8 + q;
        int r = idx >> 5, l = idx & 31;
        int i = i0 + r;
        int j = i - 31 + l;
        float pv = 0.f;
        if (j >= 0) {
            int slot = (j >> 6) & 1;
            pv = __expf(fs[FAS_W + slot*64*68 + r*68 + (j & 63)] - fs[FAS_M + r]) * fs[FAS_S + r];
        }
        fs[FAS_K + r*32 + l] = pv;
    }
    __syncthreads();

    #pragma unroll
    for (int ii = 0; ii < 4; ii++) {
        int r = ty*4 + ii;
        int i = i0 + r;
        float invs = fs[FAS_S + r];
        float s32 = 0.f;
        float c[4] = {0.f, 0.f, 0.f, 0.f};
        #pragma unroll
        for (int l = 0; l < 32; l++) {
            float pl = fs[FAS_K + r*32 + l];
            s32 += pl;
            #pragma unroll
            for (int jj = 0; jj < 4; jj++)
                c[jj] = fmaf(pl, fs[FAS_V + (l+1)*64 + tx*4+jj], c[jj]);
        }
        float far2 = 1.f - s32;
        uint32_t hi2[2], lo2[2];
        #pragma unroll
        for (int jj = 0; jj < 4; jj++)
            c[jj] = fmaf(far2, fs[FAS_V + tx*4+jj], c[jj]);
        float o0 = av[ii][0]*invs + c[0];
        float o1 = av[ii][1]*invs + c[1];
        float o2 = av[ii][2]*invs + c[2];
        float o3 = av[ii][3]*invs + c[3];
        __nv_bfloat16 h0 = __float2bfloat16(o0), h1 = __float2bfloat16(o1),
                      h2 = __float2bfloat16(o2), h3 = __float2bfloat16(o3);
        hi2[0] = pack_bf2(h0, h1); hi2[1] = pack_bf2(h2, h3);
        lo2[0] = pack_bf2(__float2bfloat16(o0 - __bfloat162float(h0)),
                          __float2bfloat16(o1 - __bfloat162float(h1)));
        lo2[1] = pack_bf2(__float2bfloat16(o2 - __bfloat162float(h2)),
                          __float2bfloat16(o3 - __bfloat162float(h3)));
        size_t o = ((size_t)(b * Tc + i)) * Ec + h * Dc + tx*4;
        *(uint2*)(g_actA_hi + o) = make_uint2(hi2[0], hi2[1]);
        *(uint2*)(g_actA_lo + o) = make_uint2(lo2[0], lo2[1]);
    }
}

// ---------------- host ----------------
extern "C" void kernel_launch(void* const* d_in, const int* in_sizes, int n_in,
                              void* d_out, int out_size)
{
    int ix, itds, ilrq, ilrk, irel, ilrm, iwqkv, ibqkv, iwpr, ibpr, irlw, irlk, irlv,
        il1w, il1b, il2w, il2b, iwfc, ibfc, iwfp, ibfp;
    if (in_sizes[4] == 3 * 1024 * 1024) {
        ix=0; itds=1; ilrq=2; ilrk=3; iwqkv=4; ibqkv=5; iwpr=6; ibpr=7; irlw=8; irlk=9; irlv=10;
        il1w=11; il1b=12; il2w=13; il2b=14; iwfc=15; ibfc=16; iwfp=17; ibfp=18; irel=19; ilrm=20;
    } else {
        ix=0; itds=1; ilrq=2; ilrk=3; irel=4; ilrm=5; iwqkv=6; ibqkv=7; iwpr=8; ibpr=9; irlw=10;
        irlk=11; irlv=12; il1w=13; il1b=14; il2w=15; il2b=16; iwfc=17; ibfc=18; iwfp=19; ibfp=20;
    }
    const float* x    = (const float*)d_in[ix];
    const float* tds  = (const float*)d_in[itds];
    const float* LRQ  = (const float*)d_in[ilrq];
    const float* LRK  = (const float*)d_in[ilrk];
    const int*   rel  = (const int*)  d_in[irel];
    const int*   lrm  = (const int*)  d_in[ilrm];
    const float* Wqkv = (const float*)d_in[iwqkv];
    const float* bqkv = (const float*)d_in[ibqkv];
    const float* Wpr  = (const float*)d_in[iwpr];
    const float* bpr  = (const float*)d_in[ibpr];
    const float* relw = (const float*)d_in[irlw];
    const float* relk = (const float*)d_in[irlk];
    const float* relv = (const float*)d_in[irlv];
    const float* l1w  = (const float*)d_in[il1w];
    const float* l1b  = (const float*)d_in[il1b];
    const float* l2w  = (const float*)d_in[il2w];
    const float* l2b  = (const float*)d_in[il2b];
    const float* Wfc  = (const float*)d_in[iwfc];
    const float* bfc  = (const float*)d_in[ibfc];
    const float* Wfp  = (const float*)d_in[iwfp];
    const float* bfp  = (const float*)d_in[ibfp];
    float* out = (float*)d_out;

    float *p_q, *p_k, *p_qrk, *p_lr1, *p_lr2, *p_x2;
    __nv_bfloat16 *aAh, *aAl, *aBh, *aBl, *wth, *wtl;
    __nv_bfloat16 *qh, *ql, *kh, *kl, *lrqh, *lrql, *lrkh, *lrkl;
    cudaGetSymbolAddress((void**)&p_q,   g_q);
    cudaGetSymbolAddress((void**)&p_k,   g_k);
    cudaGetSymbolAddress((void**)&p_qrk, g_qrk);
    cudaGetSymbolAddress((void**)&p_lr1, g_lr1);
    cudaGetSymbolAddress((void**)&p_lr2, g_lr2);
    cudaGetSymbolAddress((void**)&p_x2,  g_x2);
    cudaGetSymbolAddress((void**)&aAh,   g_actA_hi);
    cudaGetSymbolAddress((void**)&aAl,   g_actA_lo);
    cudaGetSymbolAddress((void**)&aBh,   g_actB_hi);
    cudaGetSymbolAddress((void**)&aBl,   g_actB_lo);
    cudaGetSymbolAddress((void**)&wth,   g_wt_hi);
    cudaGetSymbolAddress((void**)&wtl,   g_wt_lo);
    cudaGetSymbolAddress((void**)&qh,    g_qh);
    cudaGetSymbolAddress((void**)&ql,    g_ql);
    cudaGetSymbolAddress((void**)&kh,    g_kh);
    cudaGetSymbolAddress((void**)&kl,    g_kl);
    cudaGetSymbolAddress((void**)&lrqh,  g_lrqh);
    cudaGetSymbolAddress((void**)&lrql,  g_lrql);
    cudaGetSymbolAddress((void**)&lrkh,  g_lrkh);
    cudaGetSymbolAddress((void**)&lrkl,  g_lrkl);

    cudaFuncSetAttribute((const void*)fused_attn_kernel,
                         cudaFuncAttributeMaxDynamicSharedMemorySize, FA_BYTES);
    cudaFuncSetAttribute((const void*)mma_gemm<4,3>, cudaFuncAttributeMaxDynamicSharedMemorySize, GEMM_SMEM);
    cudaFuncSetAttribute((const void*)mma_gemm<2,3>, cudaFuncAttributeMaxDynamicSharedMemorySize, GEMM_SMEM);
    cudaFuncSetAttribute((const void*)mma_gemm<3,2>, cudaFuncAttributeMaxDynamicSharedMemorySize, GEMM_SMEM);
    cudaFuncSetAttribute((const void*)mma_gemm_bat, cudaFuncAttributeMaxDynamicSharedMemorySize, GEMM_SMEM);

    const int M = Bc * Tc;   // 2048

    // weight transpose/convert + LR table split-bf16 conversion
    transpose_conv_kernel<<<dim3(96, 32),  256>>>(Wqkv, wth + WOFF_QKV,  wtl + WOFF_QKV,  1024, 3072);
    transpose_conv_kernel<<<dim3(32, 32),  256>>>(Wpr,  wth + WOFF_PROJ, wtl + WOFF_PROJ, 1024, 1024);
    transpose_conv_kernel<<<dim3(128, 32), 256>>>(Wfc,  wth + WOFF_FC,   wtl + WOFF_FC,   1024, 4096);
    transpose_conv_kernel<<<dim3(32, 128), 256>>>(Wfp,  wth + WOFF_FP,   wtl + WOFF_FP,   4096, 1024);
    conv_lr_kernel<<<(Hc*NRELc*Dc)/256, 256>>>(LRQ, lrqh, lrql);
    conv_lr_kernel<<<(Hc*NRELc*Dc)/256, 256>>>(LRK, lrkh, lrkl);

    // 1) LN1 -> split bf16
    ln_bf16_kernel<<<M, 256>>>(x, l1w, l1b, aAh, aAl);
    // 2) QKV via HMMA (3-term) -> fused split into head-major q/k/v (+ q,k bf16 hi/lo)
    mma_gemm<4,3><<<dim3(24, 16), 256, GEMM_SMEM>>>(aAh, aAl, wth + WOFF_QKV, wtl + WOFF_QKV,
                                       bqkv, nullptr, nullptr, nullptr, nullptr, M, 3072, 1024);
    // 3) qrk (FFMA, small) ; lr1/lr2 via batched HMMA
    ntgemm_kernel<<<dim3(2, Tc/64, BHc), 256>>>(p_q, Tc*Dc, 0, relk, 0, 0,
                                                p_qrk, (size_t)Tc*65, Tc, 65, 1.0f);
    mma_gemm_bat<<<dim3(5, 8, BHc), 256, GEMM_SMEM>>>(qh, ql, Tc*Dc, 0,
                                                      lrkh, lrkl, NRELc*Dc, 1,
                                                      p_lr1, (size_t)Tc*NRELc,
                                                      1024, NRELc, 64, INV_SQRT_D);
    mma_gemm_bat<<<dim3(8, 5, BHc), 256, GEMM_SMEM>>>(lrqh, lrql, NRELc*Dc, 1,
                                                      kh, kl, Tc*Dc, 0,
                                                      p_lr2, (size_t)NRELc*Tc,
                                                      NRELc, 1024, 64, INV_SQRT_D);
    // 4) fused attention (occ 2)
    fused_attn_kernel<<<dim3(Tc/64, BHc), 256, FA_BYTES>>>(tds, rel, lrm, relw, relv);
    // 5) proj + residual (3-term)
    mma_gemm<2,3><<<dim3(8, 16), 256, GEMM_SMEM>>>(aAh, aAl, wth + WOFF_PROJ, wtl + WOFF_PROJ,
                                      bpr, x, p_x2, nullptr, nullptr, M, 1024, 1024);
    // 6) LN2 -> split bf16
    ln_bf16_kernel<<<M, 256>>>(p_x2, l2w, l2b, aAh, aAl);
    // 7) FC + gelu -> split bf16 (2-term: the only reduced-precision GEMM)
    mma_gemm<3,2><<<dim3(32, 16), 256, GEMM_SMEM>>>(aAh, aAl, wth + WOFF_FC, wtl + WOFF_FC,
                                       bfc, nullptr, nullptr, aBh, aBl, M, 4096, 1024);
    // 8) FP + bias + residual -> out (3-term)
    mma_gemm<2,3><<<dim3(8, 16), 256, GEMM_SMEM>>>(aBh, aBl, wth + WOFF_FP, wtl + WOFF_FP,
                                      bfp, p_x2, out, nullptr, nullptr, M, 1024, 4096);
}

// round 17
// speedup vs baseline: 1.1040x; 1.1040x over previous
#include <cuda_runtime.h>
#include <cuda_bf16.h>
#include <math.h>
#include <stdint.h>

// ---------------- problem constants ----------------
#define Bc    2
#define Tc    1024
#define Ec    1024
#define Hc    16
#define Dc    64
#define NRELc 529
#define BHc   (Bc*Hc)
#define FFc   (4*Ec)
#define INV_SQRT_D 0.125f
#define INV_SQRT3  0.57735026918962576451f

// ---------------- scratch (device globals; allocation-free) ----------------
__device__ float g_q  [BHc*Tc*Dc];
__device__ float g_k  [BHc*Tc*Dc];
__device__ float g_v  [BHc*Tc*Dc];
__device__ float g_qrk[BHc*Tc*65];
__device__ float g_lr1[BHc*Tc*NRELc];
__device__ float g_lr2[BHc*NRELc*Tc];
__device__ float g_x2 [Bc*Tc*Ec];

__device__ __nv_bfloat16 g_actA_hi[Bc*Tc*Ec];
__device__ __nv_bfloat16 g_actA_lo[Bc*Tc*Ec];
__device__ __nv_bfloat16 g_actB_hi[Bc*Tc*FFc];
__device__ __nv_bfloat16 g_actB_lo[Bc*Tc*FFc];

// bf16 split copies of q,k (head-major) and LR tables
__device__ __nv_bfloat16 g_qh[BHc*Tc*Dc], g_ql[BHc*Tc*Dc];
__device__ __nv_bfloat16 g_kh[BHc*Tc*Dc], g_kl[BHc*Tc*Dc];
__device__ __nv_bfloat16 g_lrqh[Hc*NRELc*Dc], g_lrql[Hc*NRELc*Dc];
__device__ __nv_bfloat16 g_lrkh[Hc*NRELc*Dc], g_lrkl[Hc*NRELc*Dc];

#define WOFF_QKV 0
#define WOFF_PROJ (3072*1024)
#define WOFF_FC  (WOFF_PROJ + 1024*1024)
#define WOFF_FP  (WOFF_FC + 4096*1024)
#define WT_TOTAL (WOFF_FP + 1024*4096)
__device__ __nv_bfloat16 g_wt_hi[WT_TOTAL];
__device__ __nv_bfloat16 g_wt_lo[WT_TOTAL];

// ---------------- helpers ----------------
__device__ __forceinline__ float warp_sum(float v) {
    #pragma unroll
    for (int o = 16; o; o >>= 1) v += __shfl_xor_sync(0xffffffffu, v, o);
    return v;
}
__device__ __forceinline__ float gelu_f(float v) {
    const float c = 0.7978845608028654f;
    float t = tanhf(c * (v + 0.044715f * v * v * v));
    return 0.5f * v * (1.f + t);
}
__device__ __forceinline__ uint32_t smem_u32(const void* p) {
    uint32_t a;
    asm("{ .reg .u64 t; cvta.to.shared.u64 t, %1; cvt.u32.u64 %0, t; }" : "=r"(a) : "l"(p));
    return a;
}
__device__ __forceinline__ uint32_t pack_bf2(__nv_bfloat16 a, __nv_bfloat16 b) {
    __nv_bfloat162 t; t.x = a; t.y = b;
    return *(uint32_t*)&t;
}
__device__ __forceinline__ void ldsm4(uint32_t& r0, uint32_t& r1, uint32_t& r2, uint32_t& r3,
                                      uint32_t addr) {
    asm volatile("ldmatrix.sync.aligned.m8n8.x4.shared.b16 {%0,%1,%2,%3}, [%4];"
                 : "=r"(r0), "=r"(r1), "=r"(r2), "=r"(r3) : "r"(addr));
}
__device__ __forceinline__ void mma16816(float* d, uint32_t a0, uint32_t a1, uint32_t a2,
                                         uint32_t a3, uint32_t b0, uint32_t b1) {
    asm volatile(
        "mma.sync.aligned.m16n8k16.row.col.f32.bf16.bf16.f32 "
        "{%0,%1,%2,%3}, {%4,%5,%6,%7}, {%8,%9}, {%0,%1,%2,%3};"
        : "+f"(d[0]), "+f"(d[1]), "+f"(d[2]), "+f"(d[3])
        : "r"(a0), "r"(a1), "r"(a2), "r"(a3), "r"(b0), "r"(b1));
}
__device__ __forceinline__ void cpa16(uint32_t s, const void* g) {
    asm volatile("cp.async.ca.shared.global [%0], [%1], 16;" :: "r"(s), "l"(g));
}

// ---------------- LayerNorm -> split-bf16 ----------------
__global__ __launch_bounds__(256) void ln_bf16_kernel(
    const float* __restrict__ x, const float* __restrict__ gw,
    const float* __restrict__ gb,
    __nv_bfloat16* __restrict__ ohi, __nv_bfloat16* __restrict__ olo)
{
    int row = blockIdx.x;
    const float4* xr = (const float4*)(x + (size_t)row * Ec);
    float4 v = xr[threadIdx.x];
    __shared__ float red[8];
    __shared__ float bval[2];
    int wid = threadIdx.x >> 5, lane = threadIdx.x & 31;

    float s = warp_sum(v.x + v.y + v.z + v.w);
    if (lane == 0) red[wid] = s;
    __syncthreads();
    if (threadIdx.x == 0) {
        float t = 0.f;
        #pragma unroll
        for (int i = 0; i < 8; i++) t += red[i];
        bval[0] = t * (1.f / Ec);
    }
    __syncthreads();
    float mean = bval[0];
    float d0 = v.x - mean, d1 = v.y - mean, d2 = v.z - mean, d3 = v.w - mean;
    float q = warp_sum(d0*d0 + d1*d1 + d2*d2 + d3*d3);
    if (lane == 0) red[wid] = q;
    __syncthreads();
    if (threadIdx.x == 0) {
        float t = 0.f;
        #pragma unroll
        for (int i = 0; i < 8; i++) t += red[i];
        bval[1] = 1.f / (sqrtf(t / (float)(Ec - 1)) + 1e-6f);
    }
    __syncthreads();
    float inv = bval[1];
    float4 ww = ((const float4*)gw)[threadIdx.x];
    float4 bb = ((const float4*)gb)[threadIdx.x];
    float o0 = ww.x * d0 * inv + bb.x;
    float o1 = ww.y * d1 * inv + bb.y;
    float o2 = ww.z * d2 * inv + bb.z;
    float o3 = ww.w * d3 * inv + bb.w;

    __nv_bfloat16 h0 = __float2bfloat16(o0), h1 = __float2bfloat16(o1),
                  h2 = __float2bfloat16(o2), h3 = __float2bfloat16(o3);
    __nv_bfloat16 l0 = __float2bfloat16(o0 - __bfloat162float(h0));
    __nv_bfloat16 l1 = __float2bfloat16(o1 - __bfloat162float(h1));
    __nv_bfloat16 l2 = __float2bfloat16(o2 - __bfloat162float(h2));
    __nv_bfloat16 l3 = __float2bfloat16(o3 - __bfloat162float(h3));
    size_t base = (size_t)row * Ec + threadIdx.x * 4;
    *(uint2*)(ohi + base) = make_uint2(pack_bf2(h0,h1), pack_bf2(h2,h3));
    *(uint2*)(olo + base) = make_uint2(pack_bf2(l0,l1), pack_bf2(l2,l3));
}

// ---------------- weight transpose + split-bf16:  W[K,N] -> [N,K] hi/lo ----------------
__global__ __launch_bounds__(256) void transpose_conv_kernel(
    const float* __restrict__ W,
    __nv_bfloat16* __restrict__ Ohi, __nv_bfloat16* __restrict__ Olo,
    int K, int N)
{
    __shared__ float t[32][33];
    int n0 = blockIdx.x * 32, k0 = blockIdx.y * 32;
    int tx = threadIdx.x & 31, ty = threadIdx.x >> 5;
    #pragma unroll
    for (int i = ty; i < 32; i += 8)
        t[i][tx] = W[(size_t)(k0 + i) * N + n0 + tx];
    __syncthreads();
    #pragma unroll
    for (int i = ty; i < 32; i += 8) {
        float v = t[tx][i];
        __nv_bfloat16 h = __float2bfloat16(v);
        float lo = v - __bfloat162float(h);
        size_t o = (size_t)(n0 + i) * K + k0 + tx;
        Ohi[o] = h;
        Olo[o] = __float2bfloat16(lo);
    }
}

// ---------------- flat fp32 -> split-bf16 convert (LR tables) ----------------
__global__ __launch_bounds__(256) void conv_lr_kernel(
    const float* __restrict__ s, __nv_bfloat16* __restrict__ h, __nv_bfloat16* __restrict__ l)
{
    int i = blockIdx.x * 256 + threadIdx.x;
    float v = s[i];
    __nv_bfloat16 hh = __float2bfloat16(v);
    h[i] = hh;
    l[i] = __float2bfloat16(v - __bfloat162float(hh));
}

// ---------------- HMMA split-bf16 GEMM, cp.async 2-stage pipeline ----------------
// TERMS=3: Ah*Bh + Ah*Bl + Al*Bh.  TERMS=2: Ah*Bh + Ah*Bl (A quantized).
// MODE 2: bias+resid -> fp32 C | MODE 3: bias+gelu -> bf16 hi/lo
// MODE 4: QKV epilogue — bias, then scatter to head-major g_q/g_k/g_v (+ q,k bf16 hi/lo)
#define LDA 40
#define CHUNK_BYTES (128*LDA*2)
#define STAGE_BYTES (4*CHUNK_BYTES)
#define GEMM_SMEM   (2*STAGE_BYTES)
template<int MODE, int TERMS>
__global__ __launch_bounds__(256, 2) void mma_gemm(
    const __nv_bfloat16* __restrict__ Ahi, const __nv_bfloat16* __restrict__ Alo,
    const __nv_bfloat16* __restrict__ Bhi, const __nv_bfloat16* __restrict__ Blo,
    const float* __restrict__ bias, const float* __restrict__ resid,
    float* __restrict__ C,
    __nv_bfloat16* __restrict__ Ohi, __nv_bfloat16* __restrict__ Olo,
    int M, int N, int K)
{
    extern __shared__ __align__(16) __nv_bfloat16 dsm[];
    int tid = threadIdx.x, lane = tid & 31, wid = tid >> 5;
    int m0 = blockIdx.y * 128, n0 = blockIdx.x * 128;
    int wm = (wid & 1) * 64, wn = (wid >> 1) * 32;

    const __nv_bfloat16* gp0 = Ahi + (size_t)m0 * K;
    const __nv_bfloat16* gp1 = Alo + (size_t)m0 * K;
    const __nv_bfloat16* gp2 = Bhi + (size_t)n0 * K;
    const __nv_bfloat16* gp3 = Blo + (size_t)n0 * K;

    int lr = tid >> 2, lc = tid & 3;
    size_t go0 = (size_t)lr * K + lc * 8;
    size_t go1 = (size_t)(lr + 64) * K + lc * 8;
    uint32_t sb = smem_u32(dsm);
    uint32_t so0 = (uint32_t)(lr * LDA + lc * 8) * 2;
    uint32_t so1 = (uint32_t)((lr + 64) * LDA + lc * 8) * 2;

    float acc[4][4][4] = {};

    uint32_t a_off = (uint32_t)(((wm + (lane & 15)) * LDA + ((lane >> 4) << 3)) * 2);
    uint32_t b_off = (uint32_t)(((wn + ((lane >> 4) << 3) + (lane & 7)) * LDA +
                                 (((lane >> 3) & 1) << 3)) * 2);

    const int nch = K >> 5;
    {
        cpa16(sb + 0*CHUNK_BYTES + so0, gp0 + go0); cpa16(sb + 0*CHUNK_BYTES + so1, gp0 + go1);
        if (TERMS == 3) {
            cpa16(sb + 1*CHUNK_BYTES + so0, gp1 + go0); cpa16(sb + 1*CHUNK_BYTES + so1, gp1 + go1);
        }
        cpa16(sb + 2*CHUNK_BYTES + so0, gp2 + go0); cpa16(sb + 2*CHUNK_BYTES + so1, gp2 + go1);
        cpa16(sb + 3*CHUNK_BYTES + so0, gp3 + go0); cpa16(sb + 3*CHUNK_BYTES + so1, gp3 + go1);
        asm volatile("cp.async.commit_group;");
    }
    for (int ch = 0; ch < nch; ch++) {
        uint32_t cb = sb + (uint32_t)((ch & 1) ? STAGE_BYTES : 0);
        if (ch + 1 < nch) {
            uint32_t nb = sb + (uint32_t)(((ch + 1) & 1) ? STAGE_BYTES : 0);
            int kc = (ch + 1) << 5;
            cpa16(nb + 0*CHUNK_BYTES + so0, gp0 + go0 + kc); cpa16(nb + 0*CHUNK_BYTES + so1, gp0 + go1 + kc);
            if (TERMS == 3) {
                cpa16(nb + 1*CHUNK_BYTES + so0, gp1 + go0 + kc); cpa16(nb + 1*CHUNK_BYTES + so1, gp1 + go1 + kc);
            }
            cpa16(nb + 2*CHUNK_BYTES + so0, gp2 + go0 + kc); cpa16(nb + 2*CHUNK_BYTES + so1, gp2 + go1 + kc);
            cpa16(nb + 3*CHUNK_BYTES + so0, gp3 + go0 + kc); cpa16(nb + 3*CHUNK_BYTES + so1, gp3 + go1 + kc);
            asm volatile("cp.async.commit_group;");
            asm volatile("cp.async.wait_group 1;");
        } else {
            asm volatile("cp.async.wait_group 0;");
        }
        __syncthreads();

        uint32_t sA = cb, sAl = cb + CHUNK_BYTES, sB = cb + 2*CHUNK_BYTES, sBl = cb + 3*CHUNK_BYTES;
        #pragma unroll
        for (int ks = 0; ks < 2; ks++) {
            uint32_t kb = (uint32_t)(ks * 16 * 2);
            uint32_t ah[4][4], al[4][4];
            #pragma unroll
            for (int mt = 0; mt < 4; mt++) {
                uint32_t o = a_off + kb + (uint32_t)(mt * 16 * LDA * 2);
                ldsm4(ah[mt][0], ah[mt][1], ah[mt][2], ah[mt][3], sA + o);
                if (TERMS == 3)
                    ldsm4(al[mt][0], al[mt][1], al[mt][2], al[mt][3], sAl + o);
            }
            #pragma unroll
            for (int ntp = 0; ntp < 2; ntp++) {
                uint32_t o = b_off + kb + (uint32_t)(ntp * 16 * LDA * 2);
                uint32_t bh00, bh01, bh10, bh11, bl00, bl01, bl10, bl11;
                ldsm4(bh00, bh01, bh10, bh11, sB + o);
                ldsm4(bl00, bl01, bl10, bl11, sBl + o);
                #pragma unroll
                for (int mt = 0; mt < 4; mt++) {
                    mma16816(acc[mt][2*ntp+0], ah[mt][0], ah[mt][1], ah[mt][2], ah[mt][3], bh00, bh01);
                    mma16816(acc[mt][2*ntp+0], ah[mt][0], ah[mt][1], ah[mt][2], ah[mt][3], bl00, bl01);
                    if (TERMS == 3)
                        mma16816(acc[mt][2*ntp+0], al[mt][0], al[mt][1], al[mt][2], al[mt][3], bh00, bh01);
                    mma16816(acc[mt][2*ntp+1], ah[mt][0], ah[mt][1], ah[mt][2], ah[mt][3], bh10, bh11);
                    mma16816(acc[mt][2*ntp+1], ah[mt][0], ah[mt][1], ah[mt][2], ah[mt][3], bl10, bl11);
                    if (TERMS == 3)
                        mma16816(acc[mt][2*ntp+1], al[mt][0], al[mt][1], al[mt][2], al[mt][3], bh10, bh11);
                }
            }
        }
        __syncthreads();
    }

    int er = lane >> 2, ec = (lane & 3) * 2;
    #pragma unroll
    for (int mt = 0; mt < 4; mt++) {
        #pragma unroll
        for (int nt = 0; nt < 4; nt++) {
            int m = m0 + wm + mt * 16 + er;
            int n = n0 + wn + nt * 8 + ec;
            float bv0 = bias[n], bv1 = bias[n + 1];
            float v00 = acc[mt][nt][0] + bv0, v01 = acc[mt][nt][1] + bv1;
            float v10 = acc[mt][nt][2] + bv0, v11 = acc[mt][nt][3] + bv1;
            if (MODE == 4) {
                int which = n >> 10;
                int e = n & (Ec - 1);
                int h = e >> 6, d = e & 63;
                #pragma unroll
                for (int half = 0; half < 2; half++) {
                    int mm = m + half * 8;
                    float va = half ? v10 : v00;
                    float vb = half ? v11 : v01;
                    int b = mm >> 10, t = mm & (Tc - 1);
                    size_t o = (((size_t)(b * Hc + h)) * Tc + t) * Dc + d;
                    if (which == 2) {
                        *(float2*)(g_v + o) = make_float2(va, vb);
                    } else {
                        __nv_bfloat16 ha = __float2bfloat16(va), hb = __float2bfloat16(vb);
                        uint32_t hi = pack_bf2(ha, hb);
                        uint32_t lo = pack_bf2(__float2bfloat16(va - __bfloat162float(ha)),
                                               __float2bfloat16(vb - __bfloat162float(hb)));
                        if (which == 0) {
                            *(float2*)(g_q + o) = make_float2(va, vb);
                            *(uint32_t*)(g_qh + o) = hi;
                            *(uint32_t*)(g_ql + o) = lo;
                        } else {
                            *(float2*)(g_k + o) = make_float2(va, vb);
                            *(uint32_t*)(g_kh + o) = hi;
                            *(uint32_t*)(g_kl + o) = lo;
                        }
                    }
                }
                continue;
            }
            size_t g0 = (size_t)m * N + n;
            size_t g1 = (size_t)(m + 8) * N + n;
            if (MODE == 3) {
                v00 = gelu_f(v00); v01 = gelu_f(v01);
                v10 = gelu_f(v10); v11 = gelu_f(v11);
                __nv_bfloat16 h00 = __float2bfloat16(v00), h01 = __float2bfloat16(v01);
                __nv_bfloat16 h10 = __float2bfloat16(v10), h11 = __float2bfloat16(v11);
                *(uint32_t*)(Ohi + g0) = pack_bf2(h00, h01);
                *(uint32_t*)(Ohi + g1) = pack_bf2(h10, h11);
                *(uint32_t*)(Olo + g0) = pack_bf2(
                    __float2bfloat16(v00 - __bfloat162float(h00)),
                    __float2bfloat16(v01 - __bfloat162float(h01)));
                *(uint32_t*)(Olo + g1) = pack_bf2(
                    __float2bfloat16(v10 - __bfloat162float(h10)),
                    __float2bfloat16(v11 - __bfloat162float(h11)));
            } else {
                if (MODE == 2) {
                    v00 += resid[g0]; v01 += resid[g0 + 1];
                    v10 += resid[g1]; v11 += resid[g1 + 1];
                }
                *(float2*)(C + g0) = make_float2(v00, v01);
                *(float2*)(C + g1) = make_float2(v10, v11);
            }
        }
    }
}

// ---------------- batched HMMA NT GEMM (lr1 / lr2): C[bh] = scale * A @ B^T ----------------
__global__ __launch_bounds__(256, 2) void mma_gemm_bat(
    const __nv_bfloat16* __restrict__ Ahi, const __nv_bfloat16* __restrict__ Alo,
    int aStride, int aPerH,
    const __nv_bfloat16* __restrict__ Bhi, const __nv_bfloat16* __restrict__ Blo,
    int bStride, int bPerH,
    float* __restrict__ C, size_t cStride, int M, int N, int K, float scale)
{
    extern __shared__ __align__(16) __nv_bfloat16 dsm[];
    int tid = threadIdx.x, lane = tid & 31, wid = tid >> 5;
    int bh = blockIdx.z;
    int m0 = blockIdx.y * 128, n0 = blockIdx.x * 128;
    int wm = (wid & 1) * 64, wn = (wid >> 1) * 32;

    const __nv_bfloat16* pAh = Ahi + (size_t)(aPerH ? (bh & 15) : bh) * aStride;
    const __nv_bfloat16* pAl = Alo + (size_t)(aPerH ? (bh & 15) : bh) * aStride;
    const __nv_bfloat16* pBh = Bhi + (size_t)(bPerH ? (bh & 15) : bh) * bStride;
    const __nv_bfloat16* pBl = Blo + (size_t)(bPerH ? (bh & 15) : bh) * bStride;

    int lr = tid >> 2, lc = tid & 3;
    int ra0 = m0 + lr;      if (ra0 > M - 1) ra0 = M - 1;
    int ra1 = m0 + lr + 64; if (ra1 > M - 1) ra1 = M - 1;
    int rb0 = n0 + lr;      if (rb0 > N - 1) rb0 = N - 1;
    int rb1 = n0 + lr + 64; if (rb1 > N - 1) rb1 = N - 1;
    size_t gA0 = (size_t)ra0 * K + lc * 8, gA1 = (size_t)ra1 * K + lc * 8;
    size_t gB0 = (size_t)rb0 * K + lc * 8, gB1 = (size_t)rb1 * K + lc * 8;
    uint32_t sb = smem_u32(dsm);
    uint32_t so0 = (uint32_t)(lr * LDA + lc * 8) * 2;
    uint32_t so1 = (uint32_t)((lr + 64) * LDA + lc * 8) * 2;

    float acc[4][4][4] = {};

    uint32_t a_off = (uint32_t)(((wm + (lane & 15)) * LDA + ((lane >> 4) << 3)) * 2);
    uint32_t b_off = (uint32_t)(((wn + ((lane >> 4) << 3) + (lane & 7)) * LDA +
                                 (((lane >> 3) & 1) << 3)) * 2);

    const int nch = K >> 5;
    {
        cpa16(sb + 0*CHUNK_BYTES + so0, pAh + gA0); cpa16(sb + 0*CHUNK_BYTES + so1, pAh + gA1);
        cpa16(sb + 1*CHUNK_BYTES + so0, pAl + gA0); cpa16(sb + 1*CHUNK_BYTES + so1, pAl + gA1);
        cpa16(sb + 2*CHUNK_BYTES + so0, pBh + gB0); cpa16(sb + 2*CHUNK_BYTES + so1, pBh + gB1);
        cpa16(sb + 3*CHUNK_BYTES + so0, pBl + gB0); cpa16(sb + 3*CHUNK_BYTES + so1, pBl + gB1);
        asm volatile("cp.async.commit_group;");
    }
    for (int ch = 0; ch < nch; ch++) {
        uint32_t cb = sb + (uint32_t)((ch & 1) ? STAGE_BYTES : 0);
        if (ch + 1 < nch) {
            uint32_t nb = sb + (uint32_t)(((ch + 1) & 1) ? STAGE_BYTES : 0);
            int kc = (ch + 1) << 5;
            cpa16(nb + 0*CHUNK_BYTES + so0, pAh + gA0 + kc); cpa16(nb + 0*CHUNK_BYTES + so1, pAh + gA1 + kc);
            cpa16(nb + 1*CHUNK_BYTES + so0, pAl + gA0 + kc); cpa16(nb + 1*CHUNK_BYTES + so1, pAl + gA1 + kc);
            cpa16(nb + 2*CHUNK_BYTES + so0, pBh + gB0 + kc); cpa16(nb + 2*CHUNK_BYTES + so1, pBh + gB1 + kc);
            cpa16(nb + 3*CHUNK_BYTES + so0, pBl + gB0 + kc); cpa16(nb + 3*CHUNK_BYTES + so1, pBl + gB1 + kc);
            asm volatile("cp.async.commit_group;");
            asm volatile("cp.async.wait_group 1;");
        } else {
            asm volatile("cp.async.wait_group 0;");
        }
        __syncthreads();

        uint32_t sA = cb, sAl = cb + CHUNK_BYTES, sB = cb + 2*CHUNK_BYTES, sBl = cb + 3*CHUNK_BYTES;
        #pragma unroll
        for (int ks = 0; ks < 2; ks++) {
            uint32_t kb = (uint32_t)(ks * 16 * 2);
            uint32_t ah[4][4], al[4][4];
            #pragma unroll
            for (int mt = 0; mt < 4; mt++) {
                uint32_t o = a_off + kb + (uint32_t)(mt * 16 * LDA * 2);
                ldsm4(ah[mt][0], ah[mt][1], ah[mt][2], ah[mt][3], sA + o);
                ldsm4(al[mt][0], al[mt][1], al[mt][2], al[mt][3], sAl + o);
            }
            #pragma unroll
            for (int ntp = 0; ntp < 2; ntp++) {
                uint32_t o = b_off + kb + (uint32_t)(ntp * 16 * LDA * 2);
                uint32_t bh00, bh01, bh10, bh11, bl00, bl01, bl10, bl11;
                ldsm4(bh00, bh01, bh10, bh11, sB + o);
                ldsm4(bl00, bl01, bl10, bl11, sBl + o);
                #pragma unroll
                for (int mt = 0; mt < 4; mt++) {
                    mma16816(acc[mt][2*ntp+0], ah[mt][0], ah[mt][1], ah[mt][2], ah[mt][3], bh00, bh01);
                    mma16816(acc[mt][2*ntp+0], ah[mt][0], ah[mt][1], ah[mt][2], ah[mt][3], bl00, bl01);
                    mma16816(acc[mt][2*ntp+0], al[mt][0], al[mt][1], al[mt][2], al[mt][3], bh00, bh01);
                    mma16816(acc[mt][2*ntp+1], ah[mt][0], ah[mt][1], ah[mt][2], ah[mt][3], bh10, bh11);
                    mma16816(acc[mt][2*ntp+1], ah[mt][0], ah[mt][1], ah[mt][2], ah[mt][3], bl10, bl11);
                    mma16816(acc[mt][2*ntp+1], al[mt][0], al[mt][1], al[mt][2], al[mt][3], bh10, bh11);
                }
            }
        }
        __syncthreads();
    }

    int er = lane >> 2, ec = (lane & 3) * 2;
    float* Cb = C + (size_t)bh * cStride;
    #pragma unroll
    for (int mt = 0; mt < 4; mt++) {
        #pragma unroll
        for (int nt = 0; nt < 4; nt++) {
            int m = m0 + wm + mt * 16 + er;
            int n = n0 + wn + nt * 8 + ec;
            if (m < M) {
                if (n     < N) Cb[(size_t)m * N + n]     = acc[mt][nt][0] * scale;
                if (n + 1 < N) Cb[(size_t)m * N + n + 1] = acc[mt][nt][1] * scale;
            }
            if (m + 8 < M) {
                if (n     < N) Cb[(size_t)(m + 8) * N + n]     = acc[mt][nt][2] * scale;
                if (n + 1 < N) Cb[(size_t)(m + 8) * N + n + 1] = acc[mt][nt][3] * scale;
            }
        }
    }
}

// ---------------- batched NT GEMM (qrk only) ----------------
__global__ __launch_bounds__(256) void ntgemm_kernel(
    const float* __restrict__ A, int strideA, int aModH,
    const float* __restrict__ Bm, int strideB, int bModH,
    float* __restrict__ C, size_t strideC, int M, int N, float scale)
{
    int bh = blockIdx.z;
    const float* Ab = A  + (size_t)(aModH ? (bh % Hc) : bh) * strideA;
    const float* Bb = Bm + (size_t)(bModH ? (bh % Hc) : bh) * strideB;
    float* Cb = C + (size_t)bh * strideC;
    int m0 = blockIdx.y * 64, n0 = blockIdx.x * 64;
    __shared__ float As[64][68];
    __shared__ float Bs[64][68];
    int tid = threadIdx.x;
    int tr = tid >> 4, tc4 = (tid & 15) * 4;
    #pragma unroll
    for (int p = 0; p < 4; p++) {
        int r = p * 16 + tr;
        float4 a = make_float4(0.f, 0.f, 0.f, 0.f);
        if (m0 + r < M) a = *(const float4*)(Ab + (size_t)(m0 + r) * Dc + tc4);
        As[tc4+0][r] = a.x; As[tc4+1][r] = a.y; As[tc4+2][r] = a.z; As[tc4+3][r] = a.w;
        float4 b4 = make_float4(0.f, 0.f, 0.f, 0.f);
        if (n0 + r < N) b4 = *(const float4*)(Bb + (size_t)(n0 + r) * Dc + tc4);
        Bs[tc4+0][r] = b4.x; Bs[tc4+1][r] = b4.y; Bs[tc4+2][r] = b4.z; Bs[tc4+3][r] = b4.w;
    }
    __syncthreads();
    int ty = tid >> 4, tx = tid & 15;
    float acc[4][4] = {};
    #pragma unroll
    for (int k = 0; k < 64; k++) {
        float af[4], bf[4];
        *(float4*)af = *(const float4*)&As[k][ty*4];
        *(float4*)bf = *(const float4*)&Bs[k][tx*4];
        #pragma unroll
        for (int i = 0; i < 4; i++)
            #pragma unroll
            for (int j = 0; j < 4; j++)
                acc[i][j] = fmaf(af[i], bf[j], acc[i][j]);
    }
    #pragma unroll
    for (int i = 0; i < 4; i++) {
        int m = m0 + ty*4 + i;
        if (m >= M) continue;
        #pragma unroll
        for (int j = 0; j < 4; j++) {
            int n = n0 + tx*4 + j;
            if (n < N) Cb[(size_t)m * N + n] = acc[i][j] * scale;
        }
    }
}

// ---------------- fused attention (occ 1 — full register budget, no spills) ----------------
#define FAS_Q 0
#define FAS_K (64*68)
#define FAS_V (2*64*68)
#define FAS_P (3*64*68)
#define FAS_W (3*64*68 + 64*65)
#define FAS_M (FAS_W + 2*64*68)
#define FAS_S (FAS_M + 64)
#define FAS_RW (FAS_S + 64)
#define FAS_TOT (FAS_RW + 64)
#define FA_BYTES (FAS_TOT * 4)

__global__ __launch_bounds__(256, 1) void fused_attn_kernel(
    const float* __restrict__ tds, const int* __restrict__ rel,
    const int* __restrict__ lrmap, const float* __restrict__ relw,
    const float* __restrict__ rv)
{
    extern __shared__ float fs[];
    int it = (Tc/64 - 1) - blockIdx.x;
    int bh = blockIdx.y;
    int b = bh >> 4, h = bh & 15;
    int i0 = it * 64;
    int tid = threadIdx.x;
    int tr = tid >> 4, tc4 = (tid & 15) * 4;
    int ty = tid >> 4, tx = tid & 15;

    const float* Qg = g_q + (size_t)bh * Tc * Dc;
    const float* Kg = g_k + (size_t)bh * Tc * Dc;
    const float* Vg = g_v + (size_t)bh * Tc * Dc;

    #pragma unroll
    for (int p = 0; p < 4; p++) {
        int r = p * 16 + tr;
        float4 a = *(const float4*)(Qg + (size_t)(i0 + r) * Dc + tc4);
        fs[FAS_Q + (tc4+0)*68 + r] = a.x; fs[FAS_Q + (tc4+1)*68 + r] = a.y;
        fs[FAS_Q + (tc4+2)*68 + r] = a.z; fs[FAS_Q + (tc4+3)*68 + r] = a.w;
    }
    if (tid < 64) fs[FAS_RW + tid] = relw[tid * Hc + h];

    float rm[4] = {-1e30f, -1e30f, -1e30f, -1e30f};
    float rs[4] = {0.f, 0.f, 0.f, 0.f};
    float av[4][4] = {};

    for (int jt = 0; jt <= it; jt++) {
        int j0 = jt * 64;
        #pragma unroll
        for (int p = 0; p < 4; p++) {
            int r = p * 16 + tr;
            float4 kq = *(const float4*)(Kg + (size_t)(j0 + r) * Dc + tc4);
            fs[FAS_K + (tc4+0)*68 + r] = kq.x; fs[FAS_K + (tc4+1)*68 + r] = kq.y;
            fs[FAS_K + (tc4+2)*68 + r] = kq.z; fs[FAS_K + (tc4+3)*68 + r] = kq.w;
            float4 vv = *(const float4*)(Vg + (size_t)(j0 + r) * Dc + tc4);
            *(float4*)&fs[FAS_V + r*68 + tc4] = vv;
        }
        __syncthreads();

        float aw[4][4] = {};
        #pragma unroll
        for (int k = 0; k < 64; k++) {
            float af[4], bf[4];
            *(float4*)af = *(const float4*)&fs[FAS_Q + k*68 + ty*4];
            *(float4*)bf = *(const float4*)&fs[FAS_K + k*68 + tx*4];
            #pragma unroll
            for (int i = 0; i < 4; i++)
                #pragma unroll
                for (int j = 0; j < 4; j++)
                    aw[i][j] = fmaf(af[i], bf[j], aw[i][j]);
        }

        bool diag = (jt == it);
        bool far = (jt < it - 1);
        #pragma unroll
        for (int ii = 0; ii < 4; ii++) {
            int i = i0 + ty*4 + ii;
            const float* qrk_row = g_qrk + ((size_t)bh * Tc + i) * 65;
            const float* lr1_row = g_lr1 + ((size_t)bh * Tc + i) * NRELc;
            float qrk0 = qrk_row[0];
            size_t base_b  = ((size_t)b  * Tc + i) * Tc;
            size_t base_bh = ((size_t)bh * Tc + i) * Tc;
            float4 td4 = *(const float4*)(tds + base_bh + j0 + tx*4);
            int4  re4  = *(const int4*)(rel + base_b + j0 + tx*4);
            int4  lm4  = *(const int4*)(lrmap + base_b + j0 + tx*4);
            float tdv[4] = {td4.x, td4.y, td4.z, td4.w};
            int   rev[4] = {re4.x, re4.y, re4.z, re4.w};
            int   lmv[4] = {lm4.x, lm4.y, lm4.z, lm4.w};
            #pragma unroll
            for (int jj = 0; jj < 4; jj++) {
                int j = j0 + tx*4 + jj;
                float wv;
                if (diag && j > i) {
                    wv = -1e30f;
                } else {
                    float qv = qrk0;
                    if (!far) {
                        int rid = j - i + 32; if (rid < 0) rid = 0;
                        qv = qrk_row[rid];
                    }
                    wv = (aw[ii][jj] + qv) * INV_SQRT_D;
                    wv *= fs[FAS_RW + rev[jj]];
                    wv += tdv[jj];
                    int lm = lmv[jj];
                    wv = (wv + lr1_row[lm] + g_lr2[((size_t)bh * NRELc + lm) * Tc + j]) * INV_SQRT3;
                }
                aw[ii][jj] = wv;
            }
            if (jt >= it - 1)
                *(float4*)&fs[FAS_W + (jt&1)*64*68 + (ty*4+ii)*68 + tx*4] =
                    make_float4(aw[ii][0], aw[ii][1], aw[ii][2], aw[ii][3]);
        }

        float tm[4], alpha[4], rsum[4];
        #pragma unroll
        for (int ii = 0; ii < 4; ii++) {
            tm[ii] = fmaxf(fmaxf(aw[ii][0], aw[ii][1]), fmaxf(aw[ii][2], aw[ii][3]));
            #pragma unroll
            for (int o = 1; o < 16; o <<= 1)
                tm[ii] = fmaxf(tm[ii], __shfl_xor_sync(0xffffffffu, tm[ii], o));
            float mn = fmaxf(rm[ii], tm[ii]);
            alpha[ii] = __expf(rm[ii] - mn);
            rm[ii] = mn;
            float e0 = __expf(aw[ii][0] - mn), e1 = __expf(aw[ii][1] - mn);
            float e2 = __expf(aw[ii][2] - mn), e3 = __expf(aw[ii][3] - mn);
            aw[ii][0] = e0; aw[ii][1] = e1; aw[ii][2] = e2; aw[ii][3] = e3;
            rsum[ii] = e0 + e1 + e2 + e3;
            #pragma unroll
            for (int o = 1; o < 16; o <<= 1)
                rsum[ii] += __shfl_xor_sync(0xffffffffu, rsum[ii], o);
            rs[ii] = rs[ii] * alpha[ii] + rsum[ii];
        }

        #pragma unroll
        for (int ii = 0; ii < 4; ii++)
            #pragma unroll
            for (int jj = 0; jj < 4; jj++)
                fs[FAS_P + (tx*4+jj)*65 + ty*4+ii] = aw[ii][jj];
        __syncthreads();

        #pragma unroll
        for (int ii = 0; ii < 4; ii++)
            #pragma unroll
            for (int jj = 0; jj < 4; jj++)
                av[ii][jj] *= alpha[ii];
        #pragma unroll
        for (int k = 0; k < 64; k++) {
            float pf[4], vf[4];
            pf[0] = fs[FAS_P + k*65 + ty*4+0];
            pf[1] = fs[FAS_P + k*65 + ty*4+1];
            pf[2] = fs[FAS_P + k*65 + ty*4+2];
            pf[3] = fs[FAS_P + k*65 + ty*4+3];
            *(float4*)vf = *(const float4*)&fs[FAS_V + k*68 + tx*4];
            #pragma unroll
            for (int i = 0; i < 4; i++)
                #pragma unroll
                for (int j = 0; j < 4; j++)
                    av[i][j] = fmaf(pf[i], vf[j], av[i][j]);
        }
        __syncthreads();
    }

    if (tx == 0) {
        #pragma unroll
        for (int ii = 0; ii < 4; ii++) {
            fs[FAS_M + ty*4+ii] = rm[ii];
            fs[FAS_S + ty*4+ii] = 1.f / rs[ii];
        }
    }
    __syncthreads();

    for (int idx = tid; idx < 65*64; idx += 256)
        fs[FAS_V + idx] = rv[idx];
    #pragma unroll
    for (int q = 0; q < 8; q++) {
        int idx = tid * 8 + q;
        int r = idx >> 5, l = idx & 31;
        int i = i0 + r;
        int j = i - 31 + l;
        float pv = 0.f;
        if (j >= 0) {
            int slot = (j >> 6) & 1;
            pv = __expf(fs[FAS_W + slot*64*68 + r*68 + (j & 63)] - fs[FAS_M + r]) * fs[FAS_S + r];
        }
        fs[FAS_K + r*32 + l] = pv;
    }
    __syncthreads();

    #pragma unroll
    for (int ii = 0; ii < 4; ii++) {
        int r = ty*4 + ii;
        int i = i0 + r;
        float invs = fs[FAS_S + r];
        float s32 = 0.f;
        float c[4] = {0.f, 0.f, 0.f, 0.f};
        #pragma unroll
        for (int l = 0; l < 32; l++) {
            float pl = fs[FAS_K + r*32 + l];
            s32 += pl;
            #pragma unroll
            for (int jj = 0; jj < 4; jj++)
                c[jj] = fmaf(pl, fs[FAS_V + (l+1)*64 + tx*4+jj], c[jj]);
        }
        float far2 = 1.f - s32;
        uint32_t hi2[2], lo2[2];
        #pragma unroll
        for (int jj = 0; jj < 4; jj++)
            c[jj] = fmaf(far2, fs[FAS_V + tx*4+jj], c[jj]);
        float o0 = av[ii][0]*invs + c[0];
        float o1 = av[ii][1]*invs + c[1];
        float o2 = av[ii][2]*invs + c[2];
        float o3 = av[ii][3]*invs + c[3];
        __nv_bfloat16 h0 = __float2bfloat16(o0), h1 = __float2bfloat16(o1),
                      h2 = __float2bfloat16(o2), h3 = __float2bfloat16(o3);
        hi2[0] = pack_bf2(h0, h1); hi2[1] = pack_bf2(h2, h3);
        lo2[0] = pack_bf2(__float2bfloat16(o0 - __bfloat162float(h0)),
                          __float2bfloat16(o1 - __bfloat162float(h1)));
        lo2[1] = pack_bf2(__float2bfloat16(o2 - __bfloat162float(h2)),
                          __float2bfloat16(o3 - __bfloat162float(h3)));
        size_t o = ((size_t)(b * Tc + i)) * Ec + h * Dc + tx*4;
        *(uint2*)(g_actA_hi + o) = make_uint2(hi2[0], hi2[1]);
        *(uint2*)(g_actA_lo + o) = make_uint2(lo2[0], lo2[1]);
    }
}

// ---------------- host ----------------
extern "C" void kernel_launch(void* const* d_in, const int* in_sizes, int n_in,
                              void* d_out, int out_size)
{
    int ix, itds, ilrq, ilrk, irel, ilrm, iwqkv, ibqkv, iwpr, ibpr, irlw, irlk, irlv,
        il1w, il1b, il2w, il2b, iwfc, ibfc, iwfp, ibfp;
    if (in_sizes[4] == 3 * 1024 * 1024) {
        ix=0; itds=1; ilrq=2; ilrk=3; iwqkv=4; ibqkv=5; iwpr=6; ibpr=7; irlw=8; irlk=9; irlv=10;
        il1w=11; il1b=12; il2w=13; il2b=14; iwfc=15; ibfc=16; iwfp=17; ibfp=18; irel=19; ilrm=20;
    } else {
        ix=0; itds=1; ilrq=2; ilrk=3; irel=4; ilrm=5; iwqkv=6; ibqkv=7; iwpr=8; ibpr=9; irlw=10;
        irlk=11; irlv=12; il1w=13; il1b=14; il2w=15; il2b=16; iwfc=17; ibfc=18; iwfp=19; ibfp=20;
    }
    const float* x    = (const float*)d_in[ix];
    const float* tds  = (const float*)d_in[itds];
    const float* LRQ  = (const float*)d_in[ilrq];
    const float* LRK  = (const float*)d_in[ilrk];
    const int*   rel  = (const int*)  d_in[irel];
    const int*   lrm  = (const int*)  d_in[ilrm];
    const float* Wqkv = (const float*)d_in[iwqkv];
    const float* bqkv = (const float*)d_in[ibqkv];
    const float* Wpr  = (const float*)d_in[iwpr];
    const float* bpr  = (const float*)d_in[ibpr];
    const float* relw = (const float*)d_in[irlw];
    const float* relk = (const float*)d_in[irlk];
    const float* relv = (const float*)d_in[irlv];
    const float* l1w  = (const float*)d_in[il1w];
    const float* l1b  = (const float*)d_in[il1b];
    const float* l2w  = (const float*)d_in[il2w];
    const float* l2b  = (const float*)d_in[il2b];
    const float* Wfc  = (const float*)d_in[iwfc];
    const float* bfc  = (const float*)d_in[ibfc];
    const float* Wfp  = (const float*)d_in[iwfp];
    const float* bfp  = (const float*)d_in[ibfp];
    float* out = (float*)d_out;

    float *p_q, *p_k, *p_qrk, *p_lr1, *p_lr2, *p_x2;
    __nv_bfloat16 *aAh, *aAl, *aBh, *aBl, *wth, *wtl;
    __nv_bfloat16 *qh, *ql, *kh, *kl, *lrqh, *lrql, *lrkh, *lrkl;
    cudaGetSymbolAddress((void**)&p_q,   g_q);
    cudaGetSymbolAddress((void**)&p_k,   g_k);
    cudaGetSymbolAddress((void**)&p_qrk, g_qrk);
    cudaGetSymbolAddress((void**)&p_lr1, g_lr1);
    cudaGetSymbolAddress((void**)&p_lr2, g_lr2);
    cudaGetSymbolAddress((void**)&p_x2,  g_x2);
    cudaGetSymbolAddress((void**)&aAh,   g_actA_hi);
    cudaGetSymbolAddress((void**)&aAl,   g_actA_lo);
    cudaGetSymbolAddress((void**)&aBh,   g_actB_hi);
    cudaGetSymbolAddress((void**)&aBl,   g_actB_lo);
    cudaGetSymbolAddress((void**)&wth,   g_wt_hi);
    cudaGetSymbolAddress((void**)&wtl,   g_wt_lo);
    cudaGetSymbolAddress((void**)&qh,    g_qh);
    cudaGetSymbolAddress((void**)&ql,    g_ql);
    cudaGetSymbolAddress((void**)&kh,    g_kh);
    cudaGetSymbolAddress((void**)&kl,    g_kl);
    cudaGetSymbolAddress((void**)&lrqh,  g_lrqh);
    cudaGetSymbolAddress((void**)&lrql,  g_lrql);
    cudaGetSymbolAddress((void**)&lrkh,  g_lrkh);
    cudaGetSymbolAddress((void**)&lrkl,  g_lrkl);

    cudaFuncSetAttribute((const void*)fused_attn_kernel,
                         cudaFuncAttributeMaxDynamicSharedMemorySize, FA_BYTES);
    cudaFuncSetAttribute((const void*)mma_gemm<4,3>, cudaFuncAttributeMaxDynamicSharedMemorySize, GEMM_SMEM);
    cudaFuncSetAttribute((const void*)mma_gemm<2,3>, cudaFuncAttributeMaxDynamicSharedMemorySize, GEMM_SMEM);
    cudaFuncSetAttribute((const void*)mma_gemm<3,2>, cudaFuncAttributeMaxDynamicSharedMemorySize, GEMM_SMEM);
    cudaFuncSetAttribute((const void*)mma_gemm_bat, cudaFuncAttributeMaxDynamicSharedMemorySize, GEMM_SMEM);

    const int M = Bc * Tc;   // 2048

    // weight transpose/convert + LR table split-bf16 conversion
    transpose_conv_kernel<<<dim3(96, 32),  256>>>(Wqkv, wth + WOFF_QKV,  wtl + WOFF_QKV,  1024, 3072);
    transpose_conv_kernel<<<dim3(32, 32),  256>>>(Wpr,  wth + WOFF_PROJ, wtl + WOFF_PROJ, 1024, 1024);
    transpose_conv_kernel<<<dim3(128, 32), 256>>>(Wfc,  wth + WOFF_FC,   wtl + WOFF_FC,   1024, 4096);
    transpose_conv_kernel<<<dim3(32, 128), 256>>>(Wfp,  wth + WOFF_FP,   wtl + WOFF_FP,   4096, 1024);
    conv_lr_kernel<<<(Hc*NRELc*Dc)/256, 256>>>(LRQ, lrqh, lrql);
    conv_lr_kernel<<<(Hc*NRELc*Dc)/256, 256>>>(LRK, lrkh, lrkl);

    // 1) LN1 -> split bf16
    ln_bf16_kernel<<<M, 256>>>(x, l1w, l1b, aAh, aAl);
    // 2) QKV via HMMA (3-term) -> fused split into head-major q/k/v (+ q,k bf16 hi/lo)
    mma_gemm<4,3><<<dim3(24, 16), 256, GEMM_SMEM>>>(aAh, aAl, wth + WOFF_QKV, wtl + WOFF_QKV,
                                       bqkv, nullptr, nullptr, nullptr, nullptr, M, 3072, 1024);
    // 3) qrk (FFMA, small) ; lr1/lr2 via batched HMMA
    ntgemm_kernel<<<dim3(2, Tc/64, BHc), 256>>>(p_q, Tc*Dc, 0, relk, 0, 0,
                                                p_qrk, (size_t)Tc*65, Tc, 65, 1.0f);
    mma_gemm_bat<<<dim3(5, 8, BHc), 256, GEMM_SMEM>>>(qh, ql, Tc*Dc, 0,
                                                      lrkh, lrkl, NRELc*Dc, 1,
                                                      p_lr1, (size_t)Tc*NRELc,
                                                      1024, NRELc, 64, INV_SQRT_D);
    mma_gemm_bat<<<dim3(8, 5, BHc), 256, GEMM_SMEM>>>(lrqh, lrql, NRELc*Dc, 1,
                                                      kh, kl, Tc*Dc, 0,
                                                      p_lr2, (size_t)NRELc*Tc,
                                                      NRELc, 1024, 64, INV_SQRT_D);
    // 4) fused attention (occ 1)
    fused_attn_kernel<<<dim3(Tc/64, BHc), 256, FA_BYTES>>>(tds, rel, lrm, relw, relv);
    // 5) proj + residual (3-term)
    mma_gemm<2,3><<<dim3(8, 16), 256, GEMM_SMEM>>>(aAh, aAl, wth + WOFF_PROJ, wtl + WOFF_PROJ,
                                      bpr, x, p_x2, nullptr, nullptr, M, 1024, 1024);
    // 6) LN2 -> split bf16
    ln_bf16_kernel<<<M, 256>>>(p_x2, l2w, l2b, aAh, aAl);
    // 7) FC + gelu -> split bf16 (2-term: the only reduced-precision GEMM)
    mma_gemm<3,2><<<dim3(32, 16), 256, GEMM_SMEM>>>(aAh, aAl, wth + WOFF_FC, wtl + WOFF_FC,
                                       bfc, nullptr, nullptr, aBh, aBl, M, 4096, 1024);
    // 8) FP + bias + residual -> out (3-term)
    mma_gemm<2,3><<<dim3(8, 16), 256, GEMM_SMEM>>>(aBh, aBl, wth + WOFF_FP, wtl + WOFF_FP,
                                      bfp, p_x2, out, nullptr, nullptr, M, 1024, 4096);
}